// round 5
// baseline (speedup 1.0000x reference)
#include <cuda_runtime.h>
#include <cuda_bf16.h>
#include <math.h>
#include <stdint.h>

// ---------------- problem constants ----------------
#define T_TOK   2048
#define H_DIM   2048
#define LATD    1024
#define INTERD  1024
#define NE      32
#define NG      4
#define GSZ     (NE / NG)
#define TOPK    8
#define SH_INTER 4096
#define NROWS   (T_TOK * TOPK)
#define MPAD    20480            // 160 tiles * 128 rows
#define GTILES  160
#define RSCALE  2.5f

// ---------------- device scratch (static) ----------------
__device__ __align__(1024) __nv_bfloat16 gx_hi[T_TOK * H_DIM],      gx_lo[T_TOK * H_DIM];
__device__ __align__(1024) __nv_bfloat16 gfc1_hi[LATD * H_DIM],     gfc1_lo[LATD * H_DIM];
__device__ __align__(1024) __nv_bfloat16 gfc2_hi[H_DIM * LATD],     gfc2_lo[H_DIM * LATD];
__device__ __align__(1024) __nv_bfloat16 gw1_hi[NE * INTERD * LATD], gw1_lo[NE * INTERD * LATD];
__device__ __align__(1024) __nv_bfloat16 gw2_hi[NE * LATD * INTERD], gw2_lo[NE * LATD * INTERD];
__device__ __align__(1024) __nv_bfloat16 gsup_hi[SH_INTER * H_DIM], gsup_lo[SH_INTER * H_DIM];
__device__ __align__(1024) __nv_bfloat16 gsdn_hi[H_DIM * SH_INTER], gsdn_lo[H_DIM * SH_INTER];
__device__ __align__(1024) __nv_bfloat16 gxlat_hi[T_TOK * LATD],    gxlat_lo[T_TOK * LATD];
__device__ __align__(1024) __nv_bfloat16 gxg_hi[MPAD * LATD],       gxg_lo[MPAD * LATD];
__device__ __align__(1024) __nv_bfloat16 gh_hi[MPAD * INTERD],      gh_lo[MPAD * INTERD];
__device__ __align__(1024) float         gyg[MPAD * LATD];
__device__ __align__(1024) __nv_bfloat16 gylat_hi[T_TOK * LATD],    gylat_lo[T_TOK * LATD];
__device__ __align__(1024) __nv_bfloat16 gs1_hi[T_TOK * SH_INTER],  gs1_lo[T_TOK * SH_INTER];
__device__ __align__(1024) float         g_routed[T_TOK * H_DIM];

__device__ int   g_topi[NROWS];
__device__ float g_wsel[NROWS];
__device__ int   g_counts[NE];
__device__ int   g_off[NE];
__device__ int   g_cursor[NE];
__device__ int   g_gtok[MPAD];      // zero-init; pads stay 0
__device__ float g_gw[MPAD];        // zero-init; pads stay 0
__device__ int   g_rowidx[NROWS];
__device__ int   g_tile_e[GTILES];
__device__ int   g_tile_m0[GTILES];
__device__ int   g_ntiles;

// ---------------- PTX helpers ----------------
__device__ __forceinline__ uint32_t smem_u32(const void* p) {
    uint32_t a;
    asm("{ .reg .u64 t; cvta.to.shared.u64 t, %1; cvt.u32.u64 %0, t; }" : "=r"(a) : "l"(p));
    return a;
}
__device__ __forceinline__ void cp16(uint32_t dst, const void* src) {
    asm volatile("cp.async.cg.shared.global [%0], [%1], 16;" :: "r"(dst), "l"(src) : "memory");
}
__device__ __forceinline__ void ldsm4(uint32_t* r, uint32_t addr) {
    asm volatile("ldmatrix.sync.aligned.m8n8.x4.shared.b16 {%0,%1,%2,%3}, [%4];"
        : "=r"(r[0]), "=r"(r[1]), "=r"(r[2]), "=r"(r[3]) : "r"(addr));
}
__device__ __forceinline__ void mma16816(float* d, const uint32_t* a, uint32_t b0, uint32_t b1) {
    asm volatile("mma.sync.aligned.m16n8k16.row.col.f32.bf16.bf16.f32 "
        "{%0,%1,%2,%3}, {%4,%5,%6,%7}, {%8,%9}, {%0,%1,%2,%3};"
        : "+f"(d[0]), "+f"(d[1]), "+f"(d[2]), "+f"(d[3])
        : "r"(a[0]), "r"(a[1]), "r"(a[2]), "r"(a[3]), "r"(b0), "r"(b1));
}

// ---------------- fp32 -> bf16 hi/lo split ----------------
__device__ __forceinline__ void split_val(float v, __nv_bfloat16& h, __nv_bfloat16& l) {
    h = __float2bfloat16(v);
    l = __float2bfloat16(v - __bfloat162float(h));
}

__global__ void split_kernel(const float4* __restrict__ in,
                             __nv_bfloat16* __restrict__ hi,
                             __nv_bfloat16* __restrict__ lo, int n4)
{
    int i = blockIdx.x * blockDim.x + threadIdx.x;
    if (i >= n4) return;
    float4 v = in[i];
    __nv_bfloat16 h0, h1, h2, h3, l0, l1, l2, l3;
    split_val(v.x, h0, l0); split_val(v.y, h1, l1);
    split_val(v.z, h2, l2); split_val(v.w, h3, l3);
    __nv_bfloat162* hi2 = reinterpret_cast<__nv_bfloat162*>(hi);
    __nv_bfloat162* lo2 = reinterpret_cast<__nv_bfloat162*>(lo);
    hi2[i * 2]     = __nv_bfloat162(h0, h1);
    hi2[i * 2 + 1] = __nv_bfloat162(h2, h3);
    lo2[i * 2]     = __nv_bfloat162(l0, l1);
    lo2[i * 2 + 1] = __nv_bfloat162(l2, l3);
}

// ---------------- gate + routing (exact fp32) ----------------
__global__ void gate_kernel(const float* __restrict__ x,
                            const float* __restrict__ gw,
                            const float* __restrict__ gb)
{
    int t = blockIdx.x;
    __shared__ float logits[NE];
    int warp = threadIdx.x >> 5, lane = threadIdx.x & 31;
    const float* xt = x + (long)t * H_DIM;
    for (int e = warp; e < NE; e += 4) {
        const float* w = gw + (long)e * H_DIM;
        float s = 0.f;
        for (int h = lane; h < H_DIM; h += 32) s = fmaf(xt[h], w[h], s);
        #pragma unroll
        for (int o = 16; o > 0; o >>= 1) s += __shfl_down_sync(0xffffffffu, s, o);
        if (lane == 0) logits[e] = s;
    }
    __syncthreads();
    if (threadIdx.x == 0) {
        float sc[NE], sb[NE];
        #pragma unroll
        for (int e = 0; e < NE; e++) {
            float s = 1.f / (1.f + expf(-logits[e]));
            sc[e] = s; sb[e] = s + gb[e];
        }
        float gsc[NG];
        #pragma unroll
        for (int g = 0; g < NG; g++) {
            float m1 = -1e30f, m2 = -1e30f;
            #pragma unroll
            for (int j = 0; j < GSZ; j++) {
                float v = sb[g * GSZ + j];
                if (v > m1) { m2 = m1; m1 = v; } else if (v > m2) m2 = v;
            }
            gsc[g] = m1 + m2;
        }
        int g1 = 0; float b1 = gsc[0];
        for (int g = 1; g < NG; g++) if (gsc[g] > b1) { b1 = gsc[g]; g1 = g; }
        int g2 = -1; float b2 = -1e30f;
        for (int g = 0; g < NG; g++) if (g != g1 && gsc[g] > b2) { b2 = gsc[g]; g2 = g; }
        bool used[NE];
        #pragma unroll
        for (int e = 0; e < NE; e++) used[e] = !((e / GSZ) == g1 || (e / GSZ) == g2);
        float wtmp[TOPK]; float wsum = 0.f;
        #pragma unroll
        for (int k = 0; k < TOPK; k++) {
            int best = -1; float bv = -1e30f;
            for (int e = 0; e < NE; e++)
                if (!used[e] && sb[e] > bv) { bv = sb[e]; best = e; }
            used[best] = true;
            g_topi[t * TOPK + k] = best;
            wtmp[k] = sc[best]; wsum += sc[best];
        }
        float inv = RSCALE / wsum;
        #pragma unroll
        for (int k = 0; k < TOPK; k++) g_wsel[t * TOPK + k] = wtmp[k] * inv;
    }
}

__global__ void zero_counts_kernel() { if (threadIdx.x < NE) g_counts[threadIdx.x] = 0; }

__global__ void count_kernel()
{
    int i = blockIdx.x * blockDim.x + threadIdx.x;
    if (i < NROWS) atomicAdd(&g_counts[g_topi[i]], 1);
}

__global__ void scan_kernel()
{
    if (threadIdx.x == 0) {
        int s = 0, nt = 0;
        for (int e = 0; e < NE; e++) {
            g_off[e] = s; g_cursor[e] = s;
            int c = g_counts[e];
            int tiles = (c + 127) >> 7;
            for (int j = 0; j < tiles; j++) { g_tile_e[nt] = e; g_tile_m0[nt] = s + j * 128; nt++; }
            s += tiles << 7;
        }
        g_ntiles = nt;
    }
}

__global__ void scatter_kernel()
{
    int i = blockIdx.x * blockDim.x + threadIdx.x;
    if (i < NROWS) {
        int e = g_topi[i];
        int pos = atomicAdd(&g_cursor[e], 1);
        g_gtok[pos] = i / TOPK;
        g_gw[pos]   = g_wsel[i];
        g_rowidx[i] = pos;
    }
}

// gather xlat (bf16 pair) rows into padded expert-sorted layout
__global__ void gather_kernel()
{
    int row = blockIdx.x;
    int t = g_gtok[row];
    const uint32_t* sh = reinterpret_cast<const uint32_t*>(gxlat_hi + (long)t * LATD);
    const uint32_t* sl = reinterpret_cast<const uint32_t*>(gxlat_lo + (long)t * LATD);
    uint32_t* dh = reinterpret_cast<uint32_t*>(gxg_hi + (long)row * LATD);
    uint32_t* dl = reinterpret_cast<uint32_t*>(gxg_lo + (long)row * LATD);
    int i = threadIdx.x;
    dh[i] = sh[i]; dh[i + 256] = sh[i + 256];
    dl[i] = sl[i]; dl[i + 256] = sl[i + 256];
}

// combine: ylat[t] = sum_k yg[rowidx[t,k]]; split to bf16 pair
__global__ void combine_kernel()
{
    int t = blockIdx.x;
    int l4 = threadIdx.x;
    int ridx[TOPK];
    #pragma unroll
    for (int k = 0; k < TOPK; k++) ridx[k] = g_rowidx[t * TOPK + k];
    float4 s = make_float4(0.f, 0.f, 0.f, 0.f);
    #pragma unroll
    for (int k = 0; k < TOPK; k++) {
        const float4 v = reinterpret_cast<const float4*>(gyg + (long)ridx[k] * LATD)[l4];
        s.x += v.x; s.y += v.y; s.z += v.z; s.w += v.w;
    }
    __nv_bfloat16 h0, h1, h2, h3, l0, l1, l2, l3;
    split_val(s.x, h0, l0); split_val(s.y, h1, l1);
    split_val(s.z, h2, l2); split_val(s.w, h3, l3);
    __nv_bfloat162* hi2 = reinterpret_cast<__nv_bfloat162*>(gylat_hi + (long)t * LATD);
    __nv_bfloat162* lo2 = reinterpret_cast<__nv_bfloat162*>(gylat_lo + (long)t * LATD);
    hi2[l4 * 2]     = __nv_bfloat162(h0, h1);
    hi2[l4 * 2 + 1] = __nv_bfloat162(h2, h3);
    lo2[l4 * 2]     = __nv_bfloat162(l0, l1);
    lo2[l4 * 2 + 1] = __nv_bfloat162(l2, l3);
}

// ---------------- HMMA GEMM-NT, 3-term bf16 split, 64x64 warp tiles ----------------
// C[M,N] = A[M,K]*B[N,K]^T. CTA tile BM x BN (BM*BN = 32768, 8 warps of 64x64),
// K-tile 32, 3-stage cp.async pipeline, 1 syncthreads per k-tile.
// EPI: 0 fp32 store, 1 relu2->split, 2 relu2*rscale->split, 3 fp32+Cadd, 4 split

template<int EPI, bool GROUPED, int BM, int BN>
__global__ void __launch_bounds__(256)
hgemm(const __nv_bfloat16* __restrict__ Ah_, const __nv_bfloat16* __restrict__ Al_,
      const __nv_bfloat16* __restrict__ Bh_, const __nv_bfloat16* __restrict__ Bl_,
      float* __restrict__ Cf,
      __nv_bfloat16* __restrict__ Chi, __nv_bfloat16* __restrict__ Clo,
      const float* __restrict__ Cadd, const float* __restrict__ rsc,
      int N, int K, int expertN)
{
    constexpr int WGM = BM / 64;                 // warps along M
    constexpr int OFF_AL = BM * 64;
    constexpr int OFF_BH = 2 * BM * 64;
    constexpr int OFF_BL = 2 * BM * 64 + BN * 64;
    constexpr int STAGE  = 2 * (BM + BN) * 64;   // bytes per stage

    extern __shared__ char smem[];
    int m0, brow0;
    if (GROUPED) {
        if ((int)blockIdx.y >= g_ntiles) return;
        m0    = g_tile_m0[blockIdx.y];
        brow0 = g_tile_e[blockIdx.y] * expertN + blockIdx.x * BN;
    } else {
        m0    = blockIdx.y * BM;
        brow0 = blockIdx.x * BN;
    }
    const int col0 = blockIdx.x * BN;
    const int tid = threadIdx.x;
    const int wid = tid >> 5, lane = tid & 31;
    const uint32_t sb = smem_u32(smem);

    const __nv_bfloat16* pAh = Ah_ + (long)m0 * K;
    const __nv_bfloat16* pAl = Al_ + (long)m0 * K;
    const __nv_bfloat16* pBh = Bh_ + (long)brow0 * K;
    const __nv_bfloat16* pBl = Bl_ + (long)brow0 * K;

    // loader indices: thread -> (row wave of 64, 16B chunk)
    const int lrow = tid >> 2;                   // 0..63
    const int lch  = tid & 3;
    const uint32_t swz = (uint32_t)(lrow * 64 + ((lch ^ (lrow & 3)) << 4));

    // compute indices: 64x64 warp tile
    const int wm = (wid % WGM) * 64;
    const int wn = (wid / WGM) * 64;
    const int arow = wm + (lane & 15);
    const int brow = wn + (lane & 15);
    const int lhalf = lane >> 4;

    float acc[4][8][4];
    #pragma unroll
    for (int mi = 0; mi < 4; mi++)
        #pragma unroll
        for (int ni = 0; ni < 8; ni++)
            #pragma unroll
            for (int r = 0; r < 4; r++) acc[mi][ni][r] = 0.f;

    const int NT = K >> 5;

#define LOAD_STAGE(kt, s) do {                                                     \
    const long ko = (long)(kt) * 32 + lch * 8;                                     \
    const uint32_t base = sb + (uint32_t)(s) * STAGE;                              \
    _Pragma("unroll")                                                              \
    for (int r0 = 0; r0 < BM; r0 += 64) {                                          \
        cp16(base + (uint32_t)(r0 * 64) + swz,          pAh + (long)(r0 + lrow) * K + ko); \
        cp16(base + OFF_AL + (uint32_t)(r0 * 64) + swz, pAl + (long)(r0 + lrow) * K + ko); \
    }                                                                              \
    _Pragma("unroll")                                                              \
    for (int r0 = 0; r0 < BN; r0 += 64) {                                          \
        cp16(base + OFF_BH + (uint32_t)(r0 * 64) + swz, pBh + (long)(r0 + lrow) * K + ko); \
        cp16(base + OFF_BL + (uint32_t)(r0 * 64) + swz, pBl + (long)(r0 + lrow) * K + ko); \
    }                                                                              \
    asm volatile("cp.async.commit_group;" ::: "memory");                           \
} while (0)

    LOAD_STAGE(0, 0);
    LOAD_STAGE(1, 1);

    for (int kt = 0; kt < NT; kt++) {
        if (kt + 1 < NT) {
            asm volatile("cp.async.wait_group 1;" ::: "memory");
        } else {
            asm volatile("cp.async.wait_group 0;" ::: "memory");
        }
        __syncthreads();
        if (kt + 2 < NT) {
            int s2 = (kt + 2) % 3;
            LOAD_STAGE(kt + 2, s2);
        }

        const uint32_t sA = sb + (uint32_t)(kt % 3) * STAGE;
        #pragma unroll
        for (int ks = 0; ks < 2; ks++) {
            const uint32_t axor = (uint32_t)((((ks * 2 + lhalf) ^ (arow & 3))) << 4);
            const uint32_t bxor = (uint32_t)((((ks * 2 + lhalf) ^ (brow & 3))) << 4);
            uint32_t ah[4][4], al[4][4];
            #pragma unroll
            for (int mi = 0; mi < 4; mi++) {
                ldsm4(ah[mi], sA + (uint32_t)((arow + mi * 16) * 64) + axor);
                ldsm4(al[mi], sA + OFF_AL + (uint32_t)((arow + mi * 16) * 64) + axor);
            }
            #pragma unroll
            for (int ng = 0; ng < 4; ng++) {
                uint32_t bh[4], bl[4];
                const uint32_t bo = (uint32_t)((brow + ng * 16) * 64);
                ldsm4(bh, sA + OFF_BH + bo + bxor);
                ldsm4(bl, sA + OFF_BL + bo + bxor);
                #pragma unroll
                for (int mi = 0; mi < 4; mi++) {
                    mma16816(acc[mi][ng * 2],     ah[mi], bh[0], bh[2]);
                    mma16816(acc[mi][ng * 2 + 1], ah[mi], bh[1], bh[3]);
                    mma16816(acc[mi][ng * 2],     ah[mi], bl[0], bl[2]);
                    mma16816(acc[mi][ng * 2 + 1], ah[mi], bl[1], bl[3]);
                    mma16816(acc[mi][ng * 2],     al[mi], bh[0], bh[2]);
                    mma16816(acc[mi][ng * 2 + 1], al[mi], bh[1], bh[3]);
                }
            }
        }
        __syncthreads();
    }
#undef LOAD_STAGE

    // epilogue
    #pragma unroll
    for (int mi = 0; mi < 4; mi++) {
        #pragma unroll
        for (int ni = 0; ni < 8; ni++) {
            const float* d = acc[mi][ni];
            const int rr = m0 + wm + mi * 16 + (lane >> 2);
            const int cc = col0 + wn + ni * 8 + (lane & 3) * 2;
            #pragma unroll
            for (int half = 0; half < 2; half++) {
                const int r = rr + half * 8;
                float v0 = d[half * 2], v1 = d[half * 2 + 1];
                if (EPI == 0) {
                    *reinterpret_cast<float2*>(&Cf[(long)r * N + cc]) = make_float2(v0, v1);
                } else if (EPI == 3) {
                    const float2 a = *reinterpret_cast<const float2*>(&Cadd[(long)r * N + cc]);
                    *reinterpret_cast<float2*>(&Cf[(long)r * N + cc]) =
                        make_float2(v0 + a.x, v1 + a.y);
                } else {
                    if (EPI == 1) {
                        float u0 = fmaxf(v0, 0.f); v0 = u0 * u0;
                        float u1 = fmaxf(v1, 0.f); v1 = u1 * u1;
                    } else if (EPI == 2) {
                        const float w = rsc[r];
                        float u0 = fmaxf(v0, 0.f); v0 = u0 * u0 * w;
                        float u1 = fmaxf(v1, 0.f); v1 = u1 * u1 * w;
                    }
                    __nv_bfloat16 h0, l0, h1, l1;
                    split_val(v0, h0, l0); split_val(v1, h1, l1);
                    *reinterpret_cast<__nv_bfloat162*>(&Chi[(long)r * N + cc]) = __nv_bfloat162(h0, h1);
                    *reinterpret_cast<__nv_bfloat162*>(&Clo[(long)r * N + cc]) = __nv_bfloat162(l0, l1);
                }
            }
        }
    }
}

// dense config: BM=256, BN=128; grouped config: BM=128, BN=256
#define SMEM_DENSE   (3 * 2 * (256 + 128) * 64)
#define SMEM_GROUPED (3 * 2 * (128 + 256) * 64)

// ---------------- host ----------------
static void* sym(const void* s) { void* p; cudaGetSymbolAddress(&p, s); return p; }

extern "C" void kernel_launch(void* const* d_in, const int* in_sizes, int n_in,
                              void* d_out, int out_size)
{
    const float* x      = (const float*)d_in[0];
    const float* gate_w = (const float*)d_in[1];
    const float* gate_b = (const float*)d_in[2];
    const float* fc1_w  = (const float*)d_in[3];
    const float* fc2_w  = (const float*)d_in[4];
    const float* w1     = (const float*)d_in[5];
    const float* w2     = (const float*)d_in[6];
    const float* sup    = (const float*)d_in[7];
    const float* sdn    = (const float*)d_in[8];
    float* out = (float*)d_out;

    __nv_bfloat16* px_hi   = (__nv_bfloat16*)sym(gx_hi);   __nv_bfloat16* px_lo   = (__nv_bfloat16*)sym(gx_lo);
    __nv_bfloat16* pfc1_hi = (__nv_bfloat16*)sym(gfc1_hi); __nv_bfloat16* pfc1_lo = (__nv_bfloat16*)sym(gfc1_lo);
    __nv_bfloat16* pfc2_hi = (__nv_bfloat16*)sym(gfc2_hi); __nv_bfloat16* pfc2_lo = (__nv_bfloat16*)sym(gfc2_lo);
    __nv_bfloat16* pw1_hi  = (__nv_bfloat16*)sym(gw1_hi);  __nv_bfloat16* pw1_lo  = (__nv_bfloat16*)sym(gw1_lo);
    __nv_bfloat16* pw2_hi  = (__nv_bfloat16*)sym(gw2_hi);  __nv_bfloat16* pw2_lo  = (__nv_bfloat16*)sym(gw2_lo);
    __nv_bfloat16* psup_hi = (__nv_bfloat16*)sym(gsup_hi); __nv_bfloat16* psup_lo = (__nv_bfloat16*)sym(gsup_lo);
    __nv_bfloat16* psdn_hi = (__nv_bfloat16*)sym(gsdn_hi); __nv_bfloat16* psdn_lo = (__nv_bfloat16*)sym(gsdn_lo);
    __nv_bfloat16* pxlat_hi = (__nv_bfloat16*)sym(gxlat_hi); __nv_bfloat16* pxlat_lo = (__nv_bfloat16*)sym(gxlat_lo);
    __nv_bfloat16* pxg_hi  = (__nv_bfloat16*)sym(gxg_hi);  __nv_bfloat16* pxg_lo  = (__nv_bfloat16*)sym(gxg_lo);
    __nv_bfloat16* ph_hi   = (__nv_bfloat16*)sym(gh_hi);   __nv_bfloat16* ph_lo   = (__nv_bfloat16*)sym(gh_lo);
    float*         pyg     = (float*)sym(gyg);
    __nv_bfloat16* pylat_hi = (__nv_bfloat16*)sym(gylat_hi); __nv_bfloat16* pylat_lo = (__nv_bfloat16*)sym(gylat_lo);
    __nv_bfloat16* ps1_hi  = (__nv_bfloat16*)sym(gs1_hi);  __nv_bfloat16* ps1_lo  = (__nv_bfloat16*)sym(gs1_lo);
    float*         prouted = (float*)sym(g_routed);
    float*         pgw     = (float*)sym(g_gw);

    cudaFuncSetAttribute((hgemm<0, false, 256, 128>), cudaFuncAttributeMaxDynamicSharedMemorySize, SMEM_DENSE);
    cudaFuncSetAttribute((hgemm<1, false, 256, 128>), cudaFuncAttributeMaxDynamicSharedMemorySize, SMEM_DENSE);
    cudaFuncSetAttribute((hgemm<3, false, 256, 128>), cudaFuncAttributeMaxDynamicSharedMemorySize, SMEM_DENSE);
    cudaFuncSetAttribute((hgemm<4, false, 256, 128>), cudaFuncAttributeMaxDynamicSharedMemorySize, SMEM_DENSE);
    cudaFuncSetAttribute((hgemm<0, true, 128, 256>),  cudaFuncAttributeMaxDynamicSharedMemorySize, SMEM_GROUPED);
    cudaFuncSetAttribute((hgemm<2, true, 128, 256>),  cudaFuncAttributeMaxDynamicSharedMemorySize, SMEM_GROUPED);

    // 1) split conversions
    split_kernel<<<(T_TOK * H_DIM / 4 + 255) / 256, 256>>>((const float4*)x, px_hi, px_lo, T_TOK * H_DIM / 4);
    split_kernel<<<(LATD * H_DIM / 4 + 255) / 256, 256>>>((const float4*)fc1_w, pfc1_hi, pfc1_lo, LATD * H_DIM / 4);
    split_kernel<<<(H_DIM * LATD / 4 + 255) / 256, 256>>>((const float4*)fc2_w, pfc2_hi, pfc2_lo, H_DIM * LATD / 4);
    split_kernel<<<(NE * INTERD * LATD / 4 + 255) / 256, 256>>>((const float4*)w1, pw1_hi, pw1_lo, NE * INTERD * LATD / 4);
    split_kernel<<<(NE * LATD * INTERD / 4 + 255) / 256, 256>>>((const float4*)w2, pw2_hi, pw2_lo, NE * LATD * INTERD / 4);
    split_kernel<<<(SH_INTER * H_DIM / 4 + 255) / 256, 256>>>((const float4*)sup, psup_hi, psup_lo, SH_INTER * H_DIM / 4);
    split_kernel<<<(H_DIM * SH_INTER / 4 + 255) / 256, 256>>>((const float4*)sdn, psdn_hi, psdn_lo, H_DIM * SH_INTER / 4);

    // 2) gate + routing
    gate_kernel<<<T_TOK, 128>>>(x, gate_w, gate_b);
    zero_counts_kernel<<<1, 32>>>();
    count_kernel<<<(NROWS + 255) / 256, 256>>>();
    scan_kernel<<<1, 32>>>();
    scatter_kernel<<<(NROWS + 255) / 256, 256>>>();

    // 3) x_lat = x @ fc1^T -> split   M=2048 N=1024 K=2048
    hgemm<4, false, 256, 128><<<dim3(LATD / 128, T_TOK / 256), 256, SMEM_DENSE>>>(
        px_hi, px_lo, pfc1_hi, pfc1_lo, nullptr, pxlat_hi, pxlat_lo,
        nullptr, nullptr, LATD, H_DIM, 0);

    // 4) gather into expert-sorted padded rows
    gather_kernel<<<MPAD, 256>>>();

    // 5) grouped: h = relu2(xg @ w1[e]^T) * gw -> split   N=1024 K=1024
    hgemm<2, true, 128, 256><<<dim3(INTERD / 256, GTILES), 256, SMEM_GROUPED>>>(
        pxg_hi, pxg_lo, pw1_hi, pw1_lo, nullptr, ph_hi, ph_lo,
        nullptr, pgw, INTERD, LATD, INTERD);

    // 6) grouped: yg = h @ w2[e]^T (fp32)   N=1024 K=1024
    hgemm<0, true, 128, 256><<<dim3(LATD / 256, GTILES), 256, SMEM_GROUPED>>>(
        ph_hi, ph_lo, pw2_hi, pw2_lo, pyg, nullptr, nullptr,
        nullptr, nullptr, LATD, INTERD, LATD);

    // 7) combine -> ylat split
    combine_kernel<<<T_TOK, 256>>>();

    // 8) routed = ylat @ fc2^T (fp32)   M=2048 N=2048 K=1024
    hgemm<0, false, 256, 128><<<dim3(H_DIM / 128, T_TOK / 256), 256, SMEM_DENSE>>>(
        pylat_hi, pylat_lo, pfc2_hi, pfc2_lo, prouted, nullptr, nullptr,
        nullptr, nullptr, H_DIM, LATD, 0);

    // 9) s1 = relu2(x @ sup^T) -> split   M=2048 N=4096 K=2048
    hgemm<1, false, 256, 128><<<dim3(SH_INTER / 128, T_TOK / 256), 256, SMEM_DENSE>>>(
        px_hi, px_lo, psup_hi, psup_lo, nullptr, ps1_hi, ps1_lo,
        nullptr, nullptr, SH_INTER, H_DIM, 0);

    // 10) out = s1 @ sdn^T + routed (fp32)   M=2048 N=2048 K=4096
    hgemm<3, false, 256, 128><<<dim3(H_DIM / 128, T_TOK / 256), 256, SMEM_DENSE>>>(
        ps1_hi, ps1_lo, psdn_hi, psdn_lo, out, nullptr, nullptr,
        prouted, nullptr, H_DIM, SH_INTER, 0);
}

// round 6
// speedup vs baseline: 1.1146x; 1.1146x over previous
#include <cuda_runtime.h>
#include <cuda_bf16.h>
#include <math.h>
#include <stdint.h>

// ---------------- problem constants ----------------
#define T_TOK   2048
#define H_DIM   2048
#define LATD    1024
#define INTERD  1024
#define NE      32
#define NG      4
#define GSZ     (NE / NG)
#define TOPK    8
#define SH_INTER 4096
#define NROWS   (T_TOK * TOPK)
#define MPAD    20480            // 160 tiles * 128 rows
#define GTILES  160
#define RSCALE  2.5f

// ---------------- device scratch (static) ----------------
__device__ __align__(1024) __nv_bfloat16 gx_hi[T_TOK * H_DIM],      gx_lo[T_TOK * H_DIM];
__device__ __align__(1024) __nv_bfloat16 gfc1_hi[LATD * H_DIM],     gfc1_lo[LATD * H_DIM];
__device__ __align__(1024) __nv_bfloat16 gfc2_hi[H_DIM * LATD],     gfc2_lo[H_DIM * LATD];
__device__ __align__(1024) __nv_bfloat16 gw1_hi[NE * INTERD * LATD], gw1_lo[NE * INTERD * LATD];
__device__ __align__(1024) __nv_bfloat16 gw2_hi[NE * LATD * INTERD], gw2_lo[NE * LATD * INTERD];
__device__ __align__(1024) __nv_bfloat16 gsup_hi[SH_INTER * H_DIM], gsup_lo[SH_INTER * H_DIM];
__device__ __align__(1024) __nv_bfloat16 gsdn_hi[H_DIM * SH_INTER], gsdn_lo[H_DIM * SH_INTER];
__device__ __align__(1024) __nv_bfloat16 gxlat_hi[T_TOK * LATD],    gxlat_lo[T_TOK * LATD];
__device__ __align__(1024) __nv_bfloat16 gxg_hi[MPAD * LATD],       gxg_lo[MPAD * LATD];
__device__ __align__(1024) __nv_bfloat16 gh_hi[MPAD * INTERD],      gh_lo[MPAD * INTERD];
__device__ __align__(1024) float         gyg[MPAD * LATD];
__device__ __align__(1024) __nv_bfloat16 gylat_hi[T_TOK * LATD],    gylat_lo[T_TOK * LATD];
__device__ __align__(1024) __nv_bfloat16 gs1_hi[T_TOK * SH_INTER],  gs1_lo[T_TOK * SH_INTER];
__device__ __align__(1024) float         g_routed[T_TOK * H_DIM];

__device__ int   g_topi[NROWS];
__device__ float g_wsel[NROWS];
__device__ int   g_counts[NE];
__device__ int   g_off[NE];
__device__ int   g_cursor[NE];
__device__ int   g_gtok[MPAD];      // zero-init; pads stay 0
__device__ float g_gw[MPAD];        // zero-init; pads stay 0
__device__ int   g_rowidx[NROWS];
__device__ int   g_tile_e[GTILES];
__device__ int   g_tile_m0[GTILES];
__device__ int   g_ntiles;

// ---------------- PTX helpers ----------------
__device__ __forceinline__ uint32_t smem_u32(const void* p) {
    uint32_t a;
    asm("{ .reg .u64 t; cvta.to.shared.u64 t, %1; cvt.u32.u64 %0, t; }" : "=r"(a) : "l"(p));
    return a;
}
__device__ __forceinline__ void cp16(uint32_t dst, const void* src) {
    asm volatile("cp.async.cg.shared.global [%0], [%1], 16;" :: "r"(dst), "l"(src) : "memory");
}
__device__ __forceinline__ void ldsm4(uint32_t* r, uint32_t addr) {
    asm volatile("ldmatrix.sync.aligned.m8n8.x4.shared.b16 {%0,%1,%2,%3}, [%4];"
        : "=r"(r[0]), "=r"(r[1]), "=r"(r[2]), "=r"(r[3]) : "r"(addr));
}
__device__ __forceinline__ void mma16816(float* d, const uint32_t* a, uint32_t b0, uint32_t b1) {
    asm volatile("mma.sync.aligned.m16n8k16.row.col.f32.bf16.bf16.f32 "
        "{%0,%1,%2,%3}, {%4,%5,%6,%7}, {%8,%9}, {%0,%1,%2,%3};"
        : "+f"(d[0]), "+f"(d[1]), "+f"(d[2]), "+f"(d[3])
        : "r"(a[0]), "r"(a[1]), "r"(a[2]), "r"(a[3]), "r"(b0), "r"(b1));
}

// ---------------- fp32 -> bf16 hi/lo split ----------------
__device__ __forceinline__ void split_val(float v, __nv_bfloat16& h, __nv_bfloat16& l) {
    h = __float2bfloat16(v);
    l = __float2bfloat16(v - __bfloat162float(h));
}

__global__ void split_kernel(const float4* __restrict__ in,
                             __nv_bfloat16* __restrict__ hi,
                             __nv_bfloat16* __restrict__ lo, int n4)
{
    int i = blockIdx.x * blockDim.x + threadIdx.x;
    if (i >= n4) return;
    float4 v = in[i];
    __nv_bfloat16 h0, h1, h2, h3, l0, l1, l2, l3;
    split_val(v.x, h0, l0); split_val(v.y, h1, l1);
    split_val(v.z, h2, l2); split_val(v.w, h3, l3);
    __nv_bfloat162* hi2 = reinterpret_cast<__nv_bfloat162*>(hi);
    __nv_bfloat162* lo2 = reinterpret_cast<__nv_bfloat162*>(lo);
    hi2[i * 2]     = __nv_bfloat162(h0, h1);
    hi2[i * 2 + 1] = __nv_bfloat162(h2, h3);
    lo2[i * 2]     = __nv_bfloat162(l0, l1);
    lo2[i * 2 + 1] = __nv_bfloat162(l2, l3);
}

// ---------------- gate + routing (exact fp32) ----------------
__global__ void gate_kernel(const float* __restrict__ x,
                            const float* __restrict__ gw,
                            const float* __restrict__ gb)
{
    int t = blockIdx.x;
    __shared__ float logits[NE];
    int warp = threadIdx.x >> 5, lane = threadIdx.x & 31;
    const float* xt = x + (long)t * H_DIM;
    for (int e = warp; e < NE; e += 4) {
        const float* w = gw + (long)e * H_DIM;
        float s = 0.f;
        for (int h = lane; h < H_DIM; h += 32) s = fmaf(xt[h], w[h], s);
        #pragma unroll
        for (int o = 16; o > 0; o >>= 1) s += __shfl_down_sync(0xffffffffu, s, o);
        if (lane == 0) logits[e] = s;
    }
    __syncthreads();
    if (threadIdx.x == 0) {
        float sc[NE], sb[NE];
        #pragma unroll
        for (int e = 0; e < NE; e++) {
            float s = 1.f / (1.f + expf(-logits[e]));
            sc[e] = s; sb[e] = s + gb[e];
        }
        float gsc[NG];
        #pragma unroll
        for (int g = 0; g < NG; g++) {
            float m1 = -1e30f, m2 = -1e30f;
            #pragma unroll
            for (int j = 0; j < GSZ; j++) {
                float v = sb[g * GSZ + j];
                if (v > m1) { m2 = m1; m1 = v; } else if (v > m2) m2 = v;
            }
            gsc[g] = m1 + m2;
        }
        int g1 = 0; float b1 = gsc[0];
        for (int g = 1; g < NG; g++) if (gsc[g] > b1) { b1 = gsc[g]; g1 = g; }
        int g2 = -1; float b2 = -1e30f;
        for (int g = 0; g < NG; g++) if (g != g1 && gsc[g] > b2) { b2 = gsc[g]; g2 = g; }
        bool used[NE];
        #pragma unroll
        for (int e = 0; e < NE; e++) used[e] = !((e / GSZ) == g1 || (e / GSZ) == g2);
        float wtmp[TOPK]; float wsum = 0.f;
        #pragma unroll
        for (int k = 0; k < TOPK; k++) {
            int best = -1; float bv = -1e30f;
            for (int e = 0; e < NE; e++)
                if (!used[e] && sb[e] > bv) { bv = sb[e]; best = e; }
            used[best] = true;
            g_topi[t * TOPK + k] = best;
            wtmp[k] = sc[best]; wsum += sc[best];
        }
        float inv = RSCALE / wsum;
        #pragma unroll
        for (int k = 0; k < TOPK; k++) g_wsel[t * TOPK + k] = wtmp[k] * inv;
    }
}

__global__ void zero_counts_kernel() { if (threadIdx.x < NE) g_counts[threadIdx.x] = 0; }

__global__ void count_kernel()
{
    int i = blockIdx.x * blockDim.x + threadIdx.x;
    if (i < NROWS) atomicAdd(&g_counts[g_topi[i]], 1);
}

__global__ void scan_kernel()
{
    if (threadIdx.x == 0) {
        int s = 0, nt = 0;
        for (int e = 0; e < NE; e++) {
            g_off[e] = s; g_cursor[e] = s;
            int c = g_counts[e];
            int tiles = (c + 127) >> 7;
            for (int j = 0; j < tiles; j++) { g_tile_e[nt] = e; g_tile_m0[nt] = s + j * 128; nt++; }
            s += tiles << 7;
        }
        g_ntiles = nt;
    }
}

__global__ void scatter_kernel()
{
    int i = blockIdx.x * blockDim.x + threadIdx.x;
    if (i < NROWS) {
        int e = g_topi[i];
        int pos = atomicAdd(&g_cursor[e], 1);
        g_gtok[pos] = i / TOPK;
        g_gw[pos]   = g_wsel[i];
        g_rowidx[i] = pos;
    }
}

// gather xlat (bf16 pair) rows into padded expert-sorted layout
__global__ void gather_kernel()
{
    int row = blockIdx.x;
    int t = g_gtok[row];
    const uint32_t* sh = reinterpret_cast<const uint32_t*>(gxlat_hi + (long)t * LATD);
    const uint32_t* sl = reinterpret_cast<const uint32_t*>(gxlat_lo + (long)t * LATD);
    uint32_t* dh = reinterpret_cast<uint32_t*>(gxg_hi + (long)row * LATD);
    uint32_t* dl = reinterpret_cast<uint32_t*>(gxg_lo + (long)row * LATD);
    int i = threadIdx.x;
    dh[i] = sh[i]; dh[i + 256] = sh[i + 256];
    dl[i] = sl[i]; dl[i + 256] = sl[i + 256];
}

// combine: ylat[t] = sum_k yg[rowidx[t,k]]; split to bf16 pair
__global__ void combine_kernel()
{
    int t = blockIdx.x;
    int l4 = threadIdx.x;
    int ridx[TOPK];
    #pragma unroll
    for (int k = 0; k < TOPK; k++) ridx[k] = g_rowidx[t * TOPK + k];
    float4 s = make_float4(0.f, 0.f, 0.f, 0.f);
    #pragma unroll
    for (int k = 0; k < TOPK; k++) {
        const float4 v = reinterpret_cast<const float4*>(gyg + (long)ridx[k] * LATD)[l4];
        s.x += v.x; s.y += v.y; s.z += v.z; s.w += v.w;
    }
    __nv_bfloat16 h0, h1, h2, h3, l0, l1, l2, l3;
    split_val(s.x, h0, l0); split_val(s.y, h1, l1);
    split_val(s.z, h2, l2); split_val(s.w, h3, l3);
    __nv_bfloat162* hi2 = reinterpret_cast<__nv_bfloat162*>(gylat_hi + (long)t * LATD);
    __nv_bfloat162* lo2 = reinterpret_cast<__nv_bfloat162*>(gylat_lo + (long)t * LATD);
    hi2[l4 * 2]     = __nv_bfloat162(h0, h1);
    hi2[l4 * 2 + 1] = __nv_bfloat162(h2, h3);
    lo2[l4 * 2]     = __nv_bfloat162(l0, l1);
    lo2[l4 * 2 + 1] = __nv_bfloat162(l2, l3);
}

// ---------------- HMMA GEMM-NT, 3-term bf16 split ----------------
// C[M,N] = A[M,K]*B[N,K]^T. 128x128x32 CTA tiles, 8 warps (4x2, 32x64 each),
// 3-stage cp.async pipeline, ONE __syncthreads per k-tile, 2 CTAs/SM.
// SMEM per stage: Ah|Al|Bh|Bl, each 128x32 bf16 = 8KB (row=64B, 4x16B XOR-swizzled).
// EPI: 0 fp32 store, 1 relu2->split, 2 relu2*rscale->split, 3 fp32+Cadd, 4 split
#define STAGE_BYTES 32768
#define GEMM_SMEM (3 * STAGE_BYTES)

template<int EPI, bool GROUPED>
__global__ void __launch_bounds__(256, 2)
hgemm(const __nv_bfloat16* __restrict__ Ah_, const __nv_bfloat16* __restrict__ Al_,
      const __nv_bfloat16* __restrict__ Bh_, const __nv_bfloat16* __restrict__ Bl_,
      float* __restrict__ Cf,
      __nv_bfloat16* __restrict__ Chi, __nv_bfloat16* __restrict__ Clo,
      const float* __restrict__ Cadd, const float* __restrict__ rsc,
      int N, int K, int expertN)
{
    extern __shared__ char smem[];
    int m0, brow0;
    if (GROUPED) {
        if ((int)blockIdx.y >= g_ntiles) return;
        m0    = g_tile_m0[blockIdx.y];
        brow0 = g_tile_e[blockIdx.y] * expertN + blockIdx.x * 128;
    } else {
        m0    = blockIdx.y * 128;
        brow0 = blockIdx.x * 128;
    }
    const int col0 = blockIdx.x * 128;
    const int tid = threadIdx.x;
    const int wid = tid >> 5, lane = tid & 31;
    const uint32_t sb = smem_u32(smem);

    const __nv_bfloat16* pAh = Ah_ + (long)m0 * K;
    const __nv_bfloat16* pAl = Al_ + (long)m0 * K;
    const __nv_bfloat16* pBh = Bh_ + (long)brow0 * K;
    const __nv_bfloat16* pBl = Bl_ + (long)brow0 * K;

    // loader indices: each thread loads 2 chunks (rows lrow, lrow+64) per array
    const int lrow = tid >> 2;
    const int lch  = tid & 3;
    const uint32_t so0 = (uint32_t)(lrow * 64 + ((lch ^ (lrow & 3)) << 4));
    const uint32_t so1 = so0 + 64 * 64;

    // compute indices: 32x64 warp tile
    const int wm = (wid & 3) * 32, wn = (wid >> 2) * 64;
    const int arow = wm + (lane & 15);
    const int brow = wn + (lane & 15);
    const int lhalf = lane >> 4;

    float acc[2][8][4];
    #pragma unroll
    for (int mi = 0; mi < 2; mi++)
        #pragma unroll
        for (int ni = 0; ni < 8; ni++)
            #pragma unroll
            for (int r = 0; r < 4; r++) acc[mi][ni][r] = 0.f;

    const int NT = K >> 5;

#define LOAD_STAGE(kt, s) do {                                                  \
    const long ko = (long)(kt) * 32 + lch * 8;                                  \
    uint32_t base = sb + (uint32_t)(s) * STAGE_BYTES;                           \
    cp16(base         + so0, pAh + (long)lrow * K + ko);                        \
    cp16(base         + so1, pAh + (long)(lrow + 64) * K + ko);                 \
    cp16(base + 8192  + so0, pAl + (long)lrow * K + ko);                        \
    cp16(base + 8192  + so1, pAl + (long)(lrow + 64) * K + ko);                 \
    cp16(base + 16384 + so0, pBh + (long)lrow * K + ko);                        \
    cp16(base + 16384 + so1, pBh + (long)(lrow + 64) * K + ko);                 \
    cp16(base + 24576 + so0, pBl + (long)lrow * K + ko);                        \
    cp16(base + 24576 + so1, pBl + (long)(lrow + 64) * K + ko);                 \
    asm volatile("cp.async.commit_group;" ::: "memory");                        \
} while (0)

    LOAD_STAGE(0, 0);
    LOAD_STAGE(1, 1);

    for (int kt = 0; kt < NT; kt++) {
        if (kt + 1 < NT) {
            asm volatile("cp.async.wait_group 1;" ::: "memory");
        } else {
            asm volatile("cp.async.wait_group 0;" ::: "memory");
        }
        __syncthreads();
        if (kt + 2 < NT) {
            LOAD_STAGE(kt + 2, (kt + 2) % 3);
        }

        const uint32_t sA = sb + (uint32_t)(kt % 3) * STAGE_BYTES;
        #pragma unroll
        for (int ks = 0; ks < 2; ks++) {
            const uint32_t axor = (uint32_t)((((ks * 2 + lhalf) ^ (arow & 3))) << 4);
            const uint32_t bxor = (uint32_t)((((ks * 2 + lhalf) ^ (brow & 3))) << 4);
            uint32_t ah[2][4], al[2][4];
            ldsm4(ah[0], sA + (uint32_t)(arow * 64) + axor);
            ldsm4(ah[1], sA + (uint32_t)((arow + 16) * 64) + axor);
            ldsm4(al[0], sA + 8192 + (uint32_t)(arow * 64) + axor);
            ldsm4(al[1], sA + 8192 + (uint32_t)((arow + 16) * 64) + axor);
            #pragma unroll
            for (int ng = 0; ng < 4; ng++) {
                uint32_t bh[4], bl[4];
                const uint32_t bo = (uint32_t)((brow + ng * 16) * 64);
                ldsm4(bh, sA + 16384 + bo + bxor);
                ldsm4(bl, sA + 24576 + bo + bxor);
                #pragma unroll
                for (int mi = 0; mi < 2; mi++) {
                    mma16816(acc[mi][ng * 2],     ah[mi], bh[0], bh[2]);
                    mma16816(acc[mi][ng * 2 + 1], ah[mi], bh[1], bh[3]);
                    mma16816(acc[mi][ng * 2],     ah[mi], bl[0], bl[2]);
                    mma16816(acc[mi][ng * 2 + 1], ah[mi], bl[1], bl[3]);
                    mma16816(acc[mi][ng * 2],     al[mi], bh[0], bh[2]);
                    mma16816(acc[mi][ng * 2 + 1], al[mi], bh[1], bh[3]);
                }
            }
        }
    }
#undef LOAD_STAGE

    // epilogue
    #pragma unroll
    for (int mi = 0; mi < 2; mi++) {
        #pragma unroll
        for (int ni = 0; ni < 8; ni++) {
            const float* d = acc[mi][ni];
            const int rr = m0 + wm + mi * 16 + (lane >> 2);
            const int cc = col0 + wn + ni * 8 + (lane & 3) * 2;
            #pragma unroll
            for (int half = 0; half < 2; half++) {
                const int r = rr + half * 8;
                float v0 = d[half * 2], v1 = d[half * 2 + 1];
                if (EPI == 0) {
                    *reinterpret_cast<float2*>(&Cf[(long)r * N + cc]) = make_float2(v0, v1);
                } else if (EPI == 3) {
                    const float2 a = *reinterpret_cast<const float2*>(&Cadd[(long)r * N + cc]);
                    *reinterpret_cast<float2*>(&Cf[(long)r * N + cc]) =
                        make_float2(v0 + a.x, v1 + a.y);
                } else {
                    if (EPI == 1) {
                        float u0 = fmaxf(v0, 0.f); v0 = u0 * u0;
                        float u1 = fmaxf(v1, 0.f); v1 = u1 * u1;
                    } else if (EPI == 2) {
                        const float w = rsc[r];
                        float u0 = fmaxf(v0, 0.f); v0 = u0 * u0 * w;
                        float u1 = fmaxf(v1, 0.f); v1 = u1 * u1 * w;
                    }
                    __nv_bfloat16 h0, l0, h1, l1;
                    split_val(v0, h0, l0); split_val(v1, h1, l1);
                    *reinterpret_cast<__nv_bfloat162*>(&Chi[(long)r * N + cc]) = __nv_bfloat162(h0, h1);
                    *reinterpret_cast<__nv_bfloat162*>(&Clo[(long)r * N + cc]) = __nv_bfloat162(l0, l1);
                }
            }
        }
    }
}

// ---------------- host ----------------
static void* sym(const void* s) { void* p; cudaGetSymbolAddress(&p, s); return p; }

extern "C" void kernel_launch(void* const* d_in, const int* in_sizes, int n_in,
                              void* d_out, int out_size)
{
    const float* x      = (const float*)d_in[0];
    const float* gate_w = (const float*)d_in[1];
    const float* gate_b = (const float*)d_in[2];
    const float* fc1_w  = (const float*)d_in[3];
    const float* fc2_w  = (const float*)d_in[4];
    const float* w1     = (const float*)d_in[5];
    const float* w2     = (const float*)d_in[6];
    const float* sup    = (const float*)d_in[7];
    const float* sdn    = (const float*)d_in[8];
    float* out = (float*)d_out;

    __nv_bfloat16* px_hi   = (__nv_bfloat16*)sym(gx_hi);   __nv_bfloat16* px_lo   = (__nv_bfloat16*)sym(gx_lo);
    __nv_bfloat16* pfc1_hi = (__nv_bfloat16*)sym(gfc1_hi); __nv_bfloat16* pfc1_lo = (__nv_bfloat16*)sym(gfc1_lo);
    __nv_bfloat16* pfc2_hi = (__nv_bfloat16*)sym(gfc2_hi); __nv_bfloat16* pfc2_lo = (__nv_bfloat16*)sym(gfc2_lo);
    __nv_bfloat16* pw1_hi  = (__nv_bfloat16*)sym(gw1_hi);  __nv_bfloat16* pw1_lo  = (__nv_bfloat16*)sym(gw1_lo);
    __nv_bfloat16* pw2_hi  = (__nv_bfloat16*)sym(gw2_hi);  __nv_bfloat16* pw2_lo  = (__nv_bfloat16*)sym(gw2_lo);
    __nv_bfloat16* psup_hi = (__nv_bfloat16*)sym(gsup_hi); __nv_bfloat16* psup_lo = (__nv_bfloat16*)sym(gsup_lo);
    __nv_bfloat16* psdn_hi = (__nv_bfloat16*)sym(gsdn_hi); __nv_bfloat16* psdn_lo = (__nv_bfloat16*)sym(gsdn_lo);
    __nv_bfloat16* pxlat_hi = (__nv_bfloat16*)sym(gxlat_hi); __nv_bfloat16* pxlat_lo = (__nv_bfloat16*)sym(gxlat_lo);
    __nv_bfloat16* pxg_hi  = (__nv_bfloat16*)sym(gxg_hi);  __nv_bfloat16* pxg_lo  = (__nv_bfloat16*)sym(gxg_lo);
    __nv_bfloat16* ph_hi   = (__nv_bfloat16*)sym(gh_hi);   __nv_bfloat16* ph_lo   = (__nv_bfloat16*)sym(gh_lo);
    float*         pyg     = (float*)sym(gyg);
    __nv_bfloat16* pylat_hi = (__nv_bfloat16*)sym(gylat_hi); __nv_bfloat16* pylat_lo = (__nv_bfloat16*)sym(gylat_lo);
    __nv_bfloat16* ps1_hi  = (__nv_bfloat16*)sym(gs1_hi);  __nv_bfloat16* ps1_lo  = (__nv_bfloat16*)sym(gs1_lo);
    float*         prouted = (float*)sym(g_routed);
    float*         pgw     = (float*)sym(g_gw);

    cudaFuncSetAttribute(hgemm<0, false>, cudaFuncAttributeMaxDynamicSharedMemorySize, GEMM_SMEM);
    cudaFuncSetAttribute(hgemm<1, false>, cudaFuncAttributeMaxDynamicSharedMemorySize, GEMM_SMEM);
    cudaFuncSetAttribute(hgemm<3, false>, cudaFuncAttributeMaxDynamicSharedMemorySize, GEMM_SMEM);
    cudaFuncSetAttribute(hgemm<4, false>, cudaFuncAttributeMaxDynamicSharedMemorySize, GEMM_SMEM);
    cudaFuncSetAttribute(hgemm<0, true >, cudaFuncAttributeMaxDynamicSharedMemorySize, GEMM_SMEM);
    cudaFuncSetAttribute(hgemm<2, true >, cudaFuncAttributeMaxDynamicSharedMemorySize, GEMM_SMEM);

    // 1) split conversions
    split_kernel<<<(T_TOK * H_DIM / 4 + 255) / 256, 256>>>((const float4*)x, px_hi, px_lo, T_TOK * H_DIM / 4);
    split_kernel<<<(LATD * H_DIM / 4 + 255) / 256, 256>>>((const float4*)fc1_w, pfc1_hi, pfc1_lo, LATD * H_DIM / 4);
    split_kernel<<<(H_DIM * LATD / 4 + 255) / 256, 256>>>((const float4*)fc2_w, pfc2_hi, pfc2_lo, H_DIM * LATD / 4);
    split_kernel<<<(NE * INTERD * LATD / 4 + 255) / 256, 256>>>((const float4*)w1, pw1_hi, pw1_lo, NE * INTERD * LATD / 4);
    split_kernel<<<(NE * LATD * INTERD / 4 + 255) / 256, 256>>>((const float4*)w2, pw2_hi, pw2_lo, NE * LATD * INTERD / 4);
    split_kernel<<<(SH_INTER * H_DIM / 4 + 255) / 256, 256>>>((const float4*)sup, psup_hi, psup_lo, SH_INTER * H_DIM / 4);
    split_kernel<<<(H_DIM * SH_INTER / 4 + 255) / 256, 256>>>((const float4*)sdn, psdn_hi, psdn_lo, H_DIM * SH_INTER / 4);

    // 2) gate + routing
    gate_kernel<<<T_TOK, 128>>>(x, gate_w, gate_b);
    zero_counts_kernel<<<1, 32>>>();
    count_kernel<<<(NROWS + 255) / 256, 256>>>();
    scan_kernel<<<1, 32>>>();
    scatter_kernel<<<(NROWS + 255) / 256, 256>>>();

    // 3) x_lat = x @ fc1^T -> split   M=2048 N=1024 K=2048
    hgemm<4, false><<<dim3(LATD / 128, T_TOK / 128), 256, GEMM_SMEM>>>(
        px_hi, px_lo, pfc1_hi, pfc1_lo, nullptr, pxlat_hi, pxlat_lo,
        nullptr, nullptr, LATD, H_DIM, 0);

    // 4) gather into expert-sorted padded rows
    gather_kernel<<<MPAD, 256>>>();

    // 5) grouped: h = relu2(xg @ w1[e]^T) * gw -> split   N=1024 K=1024
    hgemm<2, true><<<dim3(INTERD / 128, GTILES), 256, GEMM_SMEM>>>(
        pxg_hi, pxg_lo, pw1_hi, pw1_lo, nullptr, ph_hi, ph_lo,
        nullptr, pgw, INTERD, LATD, INTERD);

    // 6) grouped: yg = h @ w2[e]^T (fp32)   N=1024 K=1024
    hgemm<0, true><<<dim3(LATD / 128, GTILES), 256, GEMM_SMEM>>>(
        ph_hi, ph_lo, pw2_hi, pw2_lo, pyg, nullptr, nullptr,
        nullptr, nullptr, LATD, INTERD, LATD);

    // 7) combine -> ylat split
    combine_kernel<<<T_TOK, 256>>>();

    // 8) routed = ylat @ fc2^T (fp32)   M=2048 N=2048 K=1024
    hgemm<0, false><<<dim3(H_DIM / 128, T_TOK / 128), 256, GEMM_SMEM>>>(
        pylat_hi, pylat_lo, pfc2_hi, pfc2_lo, prouted, nullptr, nullptr,
        nullptr, nullptr, H_DIM, LATD, 0);

    // 9) s1 = relu2(x @ sup^T) -> split   M=2048 N=4096 K=2048
    hgemm<1, false><<<dim3(SH_INTER / 128, T_TOK / 128), 256, GEMM_SMEM>>>(
        px_hi, px_lo, psup_hi, psup_lo, nullptr, ps1_hi, ps1_lo,
        nullptr, nullptr, SH_INTER, H_DIM, 0);

    // 10) out = s1 @ sdn^T + routed (fp32)   M=2048 N=2048 K=4096
    hgemm<3, false><<<dim3(H_DIM / 128, T_TOK / 128), 256, GEMM_SMEM>>>(
        ps1_hi, ps1_lo, psdn_hi, psdn_lo, out, nullptr, nullptr,
        prouted, nullptr, H_DIM, SH_INTER, 0);
}

// round 7
// speedup vs baseline: 1.1278x; 1.0119x over previous
#include <cuda_runtime.h>
#include <cuda_bf16.h>
#include <math.h>
#include <stdint.h>

// ---------------- problem constants ----------------
#define T_TOK   2048
#define H_DIM   2048
#define LATD    1024
#define INTERD  1024
#define NE      32
#define NG      4
#define GSZ     (NE / NG)
#define TOPK    8
#define SH_INTER 4096
#define NROWS   (T_TOK * TOPK)
#define MPAD    20480            // 160 tiles * 128 rows
#define GTILES  160
#define RSCALE  2.5f
#define NCAT    5120             // LATD + SH_INTER

// ---------------- device scratch (static) ----------------
__device__ __align__(1024) __nv_bfloat16 gx_hi[T_TOK * H_DIM],      gx_lo[T_TOK * H_DIM];
__device__ __align__(1024) __nv_bfloat16 gB1_hi[NCAT * H_DIM],      gB1_lo[NCAT * H_DIM];   // [fc1; sup]
__device__ __align__(1024) __nv_bfloat16 gw1_hi[NE * INTERD * LATD], gw1_lo[NE * INTERD * LATD];
__device__ __align__(1024) __nv_bfloat16 gw2_hi[NE * LATD * INTERD], gw2_lo[NE * LATD * INTERD];
__device__ __align__(1024) __nv_bfloat16 gwcat_hi[H_DIM * NCAT],    gwcat_lo[H_DIM * NCAT]; // [fc2 | sdn]
__device__ __align__(1024) __nv_bfloat16 gxlat_hi[T_TOK * LATD],    gxlat_lo[T_TOK * LATD];
__device__ __align__(1024) __nv_bfloat16 gh_hi[MPAD * INTERD],      gh_lo[MPAD * INTERD];
__device__ __align__(1024) float         gyg[MPAD * LATD];
__device__ __align__(1024) __nv_bfloat16 gcat_hi[T_TOK * NCAT],     gcat_lo[T_TOK * NCAT];  // [ylat | s1]

__device__ int   g_topi[NROWS];
__device__ float g_wsel[NROWS];
__device__ int   g_counts[NE];
__device__ int   g_off[NE];
__device__ int   g_cursor[NE];
__device__ int   g_gtok[MPAD];      // zero-init; pads stay 0
__device__ float g_gw[MPAD];        // zero-init; pads stay 0
__device__ int   g_rowidx[NROWS];
__device__ int   g_tile_e[GTILES];
__device__ int   g_tile_m0[GTILES];
__device__ int   g_ntiles;

// ---------------- PTX helpers ----------------
__device__ __forceinline__ uint32_t smem_u32(const void* p) {
    uint32_t a;
    asm("{ .reg .u64 t; cvta.to.shared.u64 t, %1; cvt.u32.u64 %0, t; }" : "=r"(a) : "l"(p));
    return a;
}
__device__ __forceinline__ void cp16(uint32_t dst, const void* src) {
    asm volatile("cp.async.cg.shared.global [%0], [%1], 16;" :: "r"(dst), "l"(src) : "memory");
}
__device__ __forceinline__ void ldsm4(uint32_t* r, uint32_t addr) {
    asm volatile("ldmatrix.sync.aligned.m8n8.x4.shared.b16 {%0,%1,%2,%3}, [%4];"
        : "=r"(r[0]), "=r"(r[1]), "=r"(r[2]), "=r"(r[3]) : "r"(addr));
}
__device__ __forceinline__ void mma16816(float* d, const uint32_t* a, uint32_t b0, uint32_t b1) {
    asm volatile("mma.sync.aligned.m16n8k16.row.col.f32.bf16.bf16.f32 "
        "{%0,%1,%2,%3}, {%4,%5,%6,%7}, {%8,%9}, {%0,%1,%2,%3};"
        : "+f"(d[0]), "+f"(d[1]), "+f"(d[2]), "+f"(d[3])
        : "r"(a[0]), "r"(a[1]), "r"(a[2]), "r"(a[3]), "r"(b0), "r"(b1));
}

// ---------------- fp32 -> bf16 hi/lo split ----------------
__device__ __forceinline__ void split_val(float v, __nv_bfloat16& h, __nv_bfloat16& l) {
    h = __float2bfloat16(v);
    l = __float2bfloat16(v - __bfloat162float(h));
}

__global__ void split_kernel(const float4* __restrict__ in,
                             __nv_bfloat16* __restrict__ hi,
                             __nv_bfloat16* __restrict__ lo, int n4)
{
    int i = blockIdx.x * blockDim.x + threadIdx.x;
    if (i >= n4) return;
    float4 v = in[i];
    __nv_bfloat16 h0, h1, h2, h3, l0, l1, l2, l3;
    split_val(v.x, h0, l0); split_val(v.y, h1, l1);
    split_val(v.z, h2, l2); split_val(v.w, h3, l3);
    __nv_bfloat162* hi2 = reinterpret_cast<__nv_bfloat162*>(hi);
    __nv_bfloat162* lo2 = reinterpret_cast<__nv_bfloat162*>(lo);
    hi2[i * 2]     = __nv_bfloat162(h0, h1);
    hi2[i * 2 + 1] = __nv_bfloat162(h2, h3);
    lo2[i * 2]     = __nv_bfloat162(l0, l1);
    lo2[i * 2 + 1] = __nv_bfloat162(l2, l3);
}

// pitched split: src row length = 4<<shift floats; dst row pitch/coloff in elements
__global__ void split_pitch_kernel(const float4* __restrict__ in,
                                   __nv_bfloat16* __restrict__ hi,
                                   __nv_bfloat16* __restrict__ lo,
                                   int n4, int shift, int pitch, int coloff)
{
    int i = blockIdx.x * blockDim.x + threadIdx.x;
    if (i >= n4) return;
    float4 v = in[i];
    int row  = i >> shift;
    int col4 = i & ((1 << shift) - 1);
    long dst = (long)row * pitch + coloff + col4 * 4;
    __nv_bfloat16 h0, h1, h2, h3, l0, l1, l2, l3;
    split_val(v.x, h0, l0); split_val(v.y, h1, l1);
    split_val(v.z, h2, l2); split_val(v.w, h3, l3);
    __nv_bfloat162* hi2 = reinterpret_cast<__nv_bfloat162*>(hi + dst);
    __nv_bfloat162* lo2 = reinterpret_cast<__nv_bfloat162*>(lo + dst);
    hi2[0] = __nv_bfloat162(h0, h1);
    hi2[1] = __nv_bfloat162(h2, h3);
    lo2[0] = __nv_bfloat162(l0, l1);
    lo2[1] = __nv_bfloat162(l2, l3);
}

// ---------------- gate + routing (exact fp32) + fused count ----------------
__global__ void gate_kernel(const float* __restrict__ x,
                            const float* __restrict__ gw,
                            const float* __restrict__ gb)
{
    int t = blockIdx.x;
    __shared__ float logits[NE];
    int warp = threadIdx.x >> 5, lane = threadIdx.x & 31;
    const float* xt = x + (long)t * H_DIM;
    for (int e = warp; e < NE; e += 4) {
        const float* w = gw + (long)e * H_DIM;
        float s = 0.f;
        for (int h = lane; h < H_DIM; h += 32) s = fmaf(xt[h], w[h], s);
        #pragma unroll
        for (int o = 16; o > 0; o >>= 1) s += __shfl_down_sync(0xffffffffu, s, o);
        if (lane == 0) logits[e] = s;
    }
    __syncthreads();
    if (threadIdx.x == 0) {
        float sc[NE], sb[NE];
        #pragma unroll
        for (int e = 0; e < NE; e++) {
            float s = 1.f / (1.f + expf(-logits[e]));
            sc[e] = s; sb[e] = s + gb[e];
        }
        float gsc[NG];
        #pragma unroll
        for (int g = 0; g < NG; g++) {
            float m1 = -1e30f, m2 = -1e30f;
            #pragma unroll
            for (int j = 0; j < GSZ; j++) {
                float v = sb[g * GSZ + j];
                if (v > m1) { m2 = m1; m1 = v; } else if (v > m2) m2 = v;
            }
            gsc[g] = m1 + m2;
        }
        int g1 = 0; float b1 = gsc[0];
        for (int g = 1; g < NG; g++) if (gsc[g] > b1) { b1 = gsc[g]; g1 = g; }
        int g2 = -1; float b2 = -1e30f;
        for (int g = 0; g < NG; g++) if (g != g1 && gsc[g] > b2) { b2 = gsc[g]; g2 = g; }
        bool used[NE];
        #pragma unroll
        for (int e = 0; e < NE; e++) used[e] = !((e / GSZ) == g1 || (e / GSZ) == g2);
        float wtmp[TOPK]; float wsum = 0.f;
        #pragma unroll
        for (int k = 0; k < TOPK; k++) {
            int best = -1; float bv = -1e30f;
            for (int e = 0; e < NE; e++)
                if (!used[e] && sb[e] > bv) { bv = sb[e]; best = e; }
            used[best] = true;
            g_topi[t * TOPK + k] = best;
            atomicAdd(&g_counts[best], 1);
            wtmp[k] = sc[best]; wsum += sc[best];
        }
        float inv = RSCALE / wsum;
        #pragma unroll
        for (int k = 0; k < TOPK; k++) g_wsel[t * TOPK + k] = wtmp[k] * inv;
    }
}

__global__ void zero_counts_kernel() { if (threadIdx.x < NE) g_counts[threadIdx.x] = 0; }

__global__ void scan_kernel()
{
    if (threadIdx.x == 0) {
        int s = 0, nt = 0;
        for (int e = 0; e < NE; e++) {
            g_off[e] = s; g_cursor[e] = s;
            int c = g_counts[e];
            int tiles = (c + 127) >> 7;
            for (int j = 0; j < tiles; j++) { g_tile_e[nt] = e; g_tile_m0[nt] = s + j * 128; nt++; }
            s += tiles << 7;
        }
        g_ntiles = nt;
    }
}

__global__ void scatter_kernel()
{
    int i = blockIdx.x * blockDim.x + threadIdx.x;
    if (i < NROWS) {
        int e = g_topi[i];
        int pos = atomicAdd(&g_cursor[e], 1);
        g_gtok[pos] = i / TOPK;
        g_gw[pos]   = g_wsel[i];
        g_rowidx[i] = pos;
    }
}

// combine: ylat[t] = sum_k yg[rowidx[t,k]]; split into gcat cols 0-1023 (pitch NCAT)
__global__ void combine_kernel()
{
    int t = blockIdx.x;
    int l4 = threadIdx.x;
    int ridx[TOPK];
    #pragma unroll
    for (int k = 0; k < TOPK; k++) ridx[k] = g_rowidx[t * TOPK + k];
    float4 s = make_float4(0.f, 0.f, 0.f, 0.f);
    #pragma unroll
    for (int k = 0; k < TOPK; k++) {
        const float4 v = reinterpret_cast<const float4*>(gyg + (long)ridx[k] * LATD)[l4];
        s.x += v.x; s.y += v.y; s.z += v.z; s.w += v.w;
    }
    __nv_bfloat16 h0, h1, h2, h3, l0, l1, l2, l3;
    split_val(s.x, h0, l0); split_val(s.y, h1, l1);
    split_val(s.z, h2, l2); split_val(s.w, h3, l3);
    __nv_bfloat162* hi2 = reinterpret_cast<__nv_bfloat162*>(gcat_hi + (long)t * NCAT);
    __nv_bfloat162* lo2 = reinterpret_cast<__nv_bfloat162*>(gcat_lo + (long)t * NCAT);
    hi2[l4 * 2]     = __nv_bfloat162(h0, h1);
    hi2[l4 * 2 + 1] = __nv_bfloat162(h2, h3);
    lo2[l4 * 2]     = __nv_bfloat162(l0, l1);
    lo2[l4 * 2 + 1] = __nv_bfloat162(l2, l3);
}

// ---------------- HMMA GEMM-NT, 3-term bf16 split ----------------
// 128x128x32 CTA tiles, 8 warps (4x2, 32x64), 3-stage cp.async, 2 CTAs/SM.
// EPI: 0 fp32 store; 2 relu2*rscale -> split (pitch N); 5 mixed (col<LATD: split->C1
//      pitch LATD; else relu2 split->C2 pitch NCAT).
// GROUPED: B rows from per-expert tile table. GATHER: A row = g_gtok[padded row].
#define STAGE_BYTES 32768
#define GEMM_SMEM (3 * STAGE_BYTES)

template<int EPI, bool GROUPED, bool GATHER>
__global__ void __launch_bounds__(256, 2)
hgemm(const __nv_bfloat16* __restrict__ Ah_, const __nv_bfloat16* __restrict__ Al_,
      const __nv_bfloat16* __restrict__ Bh_, const __nv_bfloat16* __restrict__ Bl_,
      float* __restrict__ Cf,
      __nv_bfloat16* __restrict__ C1hi, __nv_bfloat16* __restrict__ C1lo,
      __nv_bfloat16* __restrict__ C2hi, __nv_bfloat16* __restrict__ C2lo,
      const float* __restrict__ rsc,
      int N, int K, int expertN)
{
    extern __shared__ char smem[];
    int m0, brow0;
    if (GROUPED) {
        if ((int)blockIdx.y >= g_ntiles) return;
        m0    = g_tile_m0[blockIdx.y];
        brow0 = g_tile_e[blockIdx.y] * expertN + blockIdx.x * 128;
    } else {
        m0    = blockIdx.y * 128;
        brow0 = blockIdx.x * 128;
    }
    const int col0 = blockIdx.x * 128;
    const int tid = threadIdx.x;
    const int wid = tid >> 5, lane = tid & 31;
    const uint32_t sb = smem_u32(smem);

    // loader indices: each thread loads rows (lrow, lrow+64) of A and B per array
    const int lrow = tid >> 2;
    const int lch  = tid & 3;
    const uint32_t so0 = (uint32_t)(lrow * 64 + ((lch ^ (lrow & 3)) << 4));
    const uint32_t so1 = so0 + 64 * 64;

    long ra0, ra1;
    if (GATHER) {
        ra0 = g_gtok[m0 + lrow];
        ra1 = g_gtok[m0 + lrow + 64];
    } else {
        ra0 = m0 + lrow;
        ra1 = m0 + lrow + 64;
    }
    const __nv_bfloat16* rowAh0 = Ah_ + ra0 * K;
    const __nv_bfloat16* rowAh1 = Ah_ + ra1 * K;
    const __nv_bfloat16* rowAl0 = Al_ + ra0 * K;
    const __nv_bfloat16* rowAl1 = Al_ + ra1 * K;
    const __nv_bfloat16* rowBh0 = Bh_ + (long)(brow0 + lrow) * K;
    const __nv_bfloat16* rowBh1 = rowBh0 + 64 * K;
    const __nv_bfloat16* rowBl0 = Bl_ + (long)(brow0 + lrow) * K;
    const __nv_bfloat16* rowBl1 = rowBl0 + 64 * K;

    // compute indices: 32x64 warp tile
    const int wm = (wid & 3) * 32, wn = (wid >> 2) * 64;
    const int arow = wm + (lane & 15);
    const int brow = wn + (lane & 15);
    const int lhalf = lane >> 4;

    float acc[2][8][4];
    #pragma unroll
    for (int mi = 0; mi < 2; mi++)
        #pragma unroll
        for (int ni = 0; ni < 8; ni++)
            #pragma unroll
            for (int r = 0; r < 4; r++) acc[mi][ni][r] = 0.f;

    const int NT = K >> 5;

#define LOAD_STAGE(kt, s) do {                                                  \
    const long ko = (long)(kt) * 32 + lch * 8;                                  \
    uint32_t base = sb + (uint32_t)(s) * STAGE_BYTES;                           \
    cp16(base         + so0, rowAh0 + ko);                                      \
    cp16(base         + so1, rowAh1 + ko);                                      \
    cp16(base + 8192  + so0, rowAl0 + ko);                                      \
    cp16(base + 8192  + so1, rowAl1 + ko);                                      \
    cp16(base + 16384 + so0, rowBh0 + ko);                                      \
    cp16(base + 16384 + so1, rowBh1 + ko);                                      \
    cp16(base + 24576 + so0, rowBl0 + ko);                                      \
    cp16(base + 24576 + so1, rowBl1 + ko);                                      \
    asm volatile("cp.async.commit_group;" ::: "memory");                        \
} while (0)

    LOAD_STAGE(0, 0);
    LOAD_STAGE(1, 1);

    for (int kt = 0; kt < NT; kt++) {
        if (kt + 1 < NT) {
            asm volatile("cp.async.wait_group 1;" ::: "memory");
        } else {
            asm volatile("cp.async.wait_group 0;" ::: "memory");
        }
        __syncthreads();
        if (kt + 2 < NT) {
            LOAD_STAGE(kt + 2, (kt + 2) % 3);
        }

        const uint32_t sA = sb + (uint32_t)(kt % 3) * STAGE_BYTES;
        #pragma unroll
        for (int ks = 0; ks < 2; ks++) {
            const uint32_t axor = (uint32_t)((((ks * 2 + lhalf) ^ (arow & 3))) << 4);
            const uint32_t bxor = (uint32_t)((((ks * 2 + lhalf) ^ (brow & 3))) << 4);
            uint32_t ah[2][4], al[2][4];
            ldsm4(ah[0], sA + (uint32_t)(arow * 64) + axor);
            ldsm4(ah[1], sA + (uint32_t)((arow + 16) * 64) + axor);
            ldsm4(al[0], sA + 8192 + (uint32_t)(arow * 64) + axor);
            ldsm4(al[1], sA + 8192 + (uint32_t)((arow + 16) * 64) + axor);
            #pragma unroll
            for (int ng = 0; ng < 4; ng++) {
                uint32_t bh[4], bl[4];
                const uint32_t bo = (uint32_t)((brow + ng * 16) * 64);
                ldsm4(bh, sA + 16384 + bo + bxor);
                ldsm4(bl, sA + 24576 + bo + bxor);
                #pragma unroll
                for (int mi = 0; mi < 2; mi++) {
                    mma16816(acc[mi][ng * 2],     ah[mi], bh[0], bh[2]);
                    mma16816(acc[mi][ng * 2 + 1], ah[mi], bh[1], bh[3]);
                    mma16816(acc[mi][ng * 2],     ah[mi], bl[0], bl[2]);
                    mma16816(acc[mi][ng * 2 + 1], ah[mi], bl[1], bl[3]);
                    mma16816(acc[mi][ng * 2],     al[mi], bh[0], bh[2]);
                    mma16816(acc[mi][ng * 2 + 1], al[mi], bh[1], bh[3]);
                }
            }
        }
    }
#undef LOAD_STAGE

    // epilogue
    const bool lowCols = (col0 < LATD);   // for EPI 5
    #pragma unroll
    for (int mi = 0; mi < 2; mi++) {
        #pragma unroll
        for (int ni = 0; ni < 8; ni++) {
            const float* d = acc[mi][ni];
            const int rr = m0 + wm + mi * 16 + (lane >> 2);
            const int cc = col0 + wn + ni * 8 + (lane & 3) * 2;
            #pragma unroll
            for (int half = 0; half < 2; half++) {
                const int r = rr + half * 8;
                float v0 = d[half * 2], v1 = d[half * 2 + 1];
                if (EPI == 0) {
                    *reinterpret_cast<float2*>(&Cf[(long)r * N + cc]) = make_float2(v0, v1);
                } else if (EPI == 2) {
                    const float w = rsc[r];
                    float u0 = fmaxf(v0, 0.f); v0 = u0 * u0 * w;
                    float u1 = fmaxf(v1, 0.f); v1 = u1 * u1 * w;
                    __nv_bfloat16 h0, l0, h1, l1;
                    split_val(v0, h0, l0); split_val(v1, h1, l1);
                    *reinterpret_cast<__nv_bfloat162*>(&C1hi[(long)r * N + cc]) = __nv_bfloat162(h0, h1);
                    *reinterpret_cast<__nv_bfloat162*>(&C1lo[(long)r * N + cc]) = __nv_bfloat162(l0, l1);
                } else { // EPI == 5
                    if (lowCols) {
                        __nv_bfloat16 h0, l0, h1, l1;
                        split_val(v0, h0, l0); split_val(v1, h1, l1);
                        *reinterpret_cast<__nv_bfloat162*>(&C1hi[(long)r * LATD + cc]) = __nv_bfloat162(h0, h1);
                        *reinterpret_cast<__nv_bfloat162*>(&C1lo[(long)r * LATD + cc]) = __nv_bfloat162(l0, l1);
                    } else {
                        float u0 = fmaxf(v0, 0.f); v0 = u0 * u0;
                        float u1 = fmaxf(v1, 0.f); v1 = u1 * u1;
                        __nv_bfloat16 h0, l0, h1, l1;
                        split_val(v0, h0, l0); split_val(v1, h1, l1);
                        *reinterpret_cast<__nv_bfloat162*>(&C2hi[(long)r * NCAT + cc]) = __nv_bfloat162(h0, h1);
                        *reinterpret_cast<__nv_bfloat162*>(&C2lo[(long)r * NCAT + cc]) = __nv_bfloat162(l0, l1);
                    }
                }
            }
        }
    }
}

// ---------------- host ----------------
static void* sym(const void* s) { void* p; cudaGetSymbolAddress(&p, s); return p; }

extern "C" void kernel_launch(void* const* d_in, const int* in_sizes, int n_in,
                              void* d_out, int out_size)
{
    const float* x      = (const float*)d_in[0];
    const float* gate_w = (const float*)d_in[1];
    const float* gate_b = (const float*)d_in[2];
    const float* fc1_w  = (const float*)d_in[3];
    const float* fc2_w  = (const float*)d_in[4];
    const float* w1     = (const float*)d_in[5];
    const float* w2     = (const float*)d_in[6];
    const float* sup    = (const float*)d_in[7];
    const float* sdn    = (const float*)d_in[8];
    float* out = (float*)d_out;

    __nv_bfloat16* px_hi   = (__nv_bfloat16*)sym(gx_hi);   __nv_bfloat16* px_lo   = (__nv_bfloat16*)sym(gx_lo);
    __nv_bfloat16* pB1_hi  = (__nv_bfloat16*)sym(gB1_hi);  __nv_bfloat16* pB1_lo  = (__nv_bfloat16*)sym(gB1_lo);
    __nv_bfloat16* pw1_hi  = (__nv_bfloat16*)sym(gw1_hi);  __nv_bfloat16* pw1_lo  = (__nv_bfloat16*)sym(gw1_lo);
    __nv_bfloat16* pw2_hi  = (__nv_bfloat16*)sym(gw2_hi);  __nv_bfloat16* pw2_lo  = (__nv_bfloat16*)sym(gw2_lo);
    __nv_bfloat16* pwc_hi  = (__nv_bfloat16*)sym(gwcat_hi); __nv_bfloat16* pwc_lo = (__nv_bfloat16*)sym(gwcat_lo);
    __nv_bfloat16* pxlat_hi = (__nv_bfloat16*)sym(gxlat_hi); __nv_bfloat16* pxlat_lo = (__nv_bfloat16*)sym(gxlat_lo);
    __nv_bfloat16* ph_hi   = (__nv_bfloat16*)sym(gh_hi);   __nv_bfloat16* ph_lo   = (__nv_bfloat16*)sym(gh_lo);
    float*         pyg     = (float*)sym(gyg);
    __nv_bfloat16* pcat_hi = (__nv_bfloat16*)sym(gcat_hi); __nv_bfloat16* pcat_lo = (__nv_bfloat16*)sym(gcat_lo);
    float*         pgw     = (float*)sym(g_gw);

    cudaFuncSetAttribute((hgemm<0, false, false>), cudaFuncAttributeMaxDynamicSharedMemorySize, GEMM_SMEM);
    cudaFuncSetAttribute((hgemm<5, false, false>), cudaFuncAttributeMaxDynamicSharedMemorySize, GEMM_SMEM);
    cudaFuncSetAttribute((hgemm<2, true, true>),   cudaFuncAttributeMaxDynamicSharedMemorySize, GEMM_SMEM);
    cudaFuncSetAttribute((hgemm<0, true, false>),  cudaFuncAttributeMaxDynamicSharedMemorySize, GEMM_SMEM);

    // 1) split conversions
    split_kernel<<<(T_TOK * H_DIM / 4 + 255) / 256, 256>>>((const float4*)x, px_hi, px_lo, T_TOK * H_DIM / 4);
    // B1 = [fc1; sup] row-stacked (both contiguous K=H_DIM rows)
    split_kernel<<<(LATD * H_DIM / 4 + 255) / 256, 256>>>((const float4*)fc1_w, pB1_hi, pB1_lo, LATD * H_DIM / 4);
    split_kernel<<<(SH_INTER * H_DIM / 4 + 255) / 256, 256>>>((const float4*)sup,
        pB1_hi + (long)LATD * H_DIM, pB1_lo + (long)LATD * H_DIM, SH_INTER * H_DIM / 4);
    split_kernel<<<(NE * INTERD * LATD / 4 + 255) / 256, 256>>>((const float4*)w1, pw1_hi, pw1_lo, NE * INTERD * LATD / 4);
    split_kernel<<<(NE * LATD * INTERD / 4 + 255) / 256, 256>>>((const float4*)w2, pw2_hi, pw2_lo, NE * LATD * INTERD / 4);
    // wcat = [fc2 | sdn] col-concat, pitch NCAT
    split_pitch_kernel<<<(H_DIM * LATD / 4 + 255) / 256, 256>>>((const float4*)fc2_w,
        pwc_hi, pwc_lo, H_DIM * LATD / 4, 8, NCAT, 0);
    split_pitch_kernel<<<(H_DIM * SH_INTER / 4 + 255) / 256, 256>>>((const float4*)sdn,
        pwc_hi, pwc_lo, H_DIM * SH_INTER / 4, 10, NCAT, LATD);

    // 2) gate + routing (count fused into gate)
    zero_counts_kernel<<<1, 32>>>();
    gate_kernel<<<T_TOK, 128>>>(x, gate_w, gate_b);
    scan_kernel<<<1, 32>>>();
    scatter_kernel<<<(NROWS + 255) / 256, 256>>>();

    // 3) merged: [x_lat | s1] = x @ [fc1; sup]^T   M=2048 N=5120 K=2048
    //    cols <1024 -> split to xlat; cols >=1024 -> relu2 split to gcat
    hgemm<5, false, false><<<dim3(NCAT / 128, T_TOK / 128), 256, GEMM_SMEM>>>(
        px_hi, px_lo, pB1_hi, pB1_lo, nullptr,
        pxlat_hi, pxlat_lo, pcat_hi, pcat_lo, nullptr, NCAT, H_DIM, 0);

    // 4) grouped+gathered: h = relu2(xlat[gtok] @ w1[e]^T) * gw   N=1024 K=1024
    hgemm<2, true, true><<<dim3(INTERD / 128, GTILES), 256, GEMM_SMEM>>>(
        pxlat_hi, pxlat_lo, pw1_hi, pw1_lo, nullptr,
        ph_hi, ph_lo, nullptr, nullptr, pgw, INTERD, LATD, INTERD);

    // 5) grouped: yg = h @ w2[e]^T (fp32)   N=1024 K=1024
    hgemm<0, true, false><<<dim3(LATD / 128, GTILES), 256, GEMM_SMEM>>>(
        ph_hi, ph_lo, pw2_hi, pw2_lo, pyg,
        nullptr, nullptr, nullptr, nullptr, nullptr, LATD, INTERD, LATD);

    // 6) combine -> gcat cols 0-1023
    combine_kernel<<<T_TOK, 256>>>();

    // 7) merged final: out = [ylat | s1] @ [fc2 | sdn]^T   M=2048 N=2048 K=5120
    hgemm<0, false, false><<<dim3(H_DIM / 128, T_TOK / 128), 256, GEMM_SMEM>>>(
        pcat_hi, pcat_lo, pwc_hi, pwc_lo, out,
        nullptr, nullptr, nullptr, nullptr, nullptr, H_DIM, NCAT, 0);
}